// round 16
// baseline (speedup 1.0000x reference)
#include <cuda_runtime.h>
#include <cuda_fp16.h>
#include <cstdint>
#include <cstddef>

#define BATCH   2
#define LSEQ    2048
#define BL      4096
#define DMODEL  1024
#define DHALF   512
#define DINNER  1024
#define DSTATE  128
#define NH      16
#define HD      64
#define CONVDIM 1280
#define DPROJ   2320
#define CH      32
#define NCH     (LSEQ / CH)
#define DBH     64

// ---------------- scratch ----------------
__device__ __half g_uh[2][BL][DHALF];
__device__ __half g_zxh[2][BL][DPROJ];
__device__ float  g_xc[2][BL][CONVDIM];
__device__ float  g_dt[2][BL][NH];
__device__ float  g_ldA[2][BL][NH];
__device__ float  g_y[2][BL][DINNER];
__device__ __half g_yh[2][BL][DINNER];
__device__ __half g_odh[BL][DMODEL];
__device__ __half wh_in[2][DPROJ * DHALF];
__device__ __half wh_out[2][DHALF * DINNER];
__device__ __half wh_op[DMODEL * DMODEL];
__device__ float  g_U[DBH][NCH][HD][DSTATE];    // U[p][n] layout
__device__ float  g_lam[DBH][NCH];
__device__ float  g_et[DBH][NCH][CH];

// ---------------- helpers ----------------
__device__ __forceinline__ void cp16(uint32_t dst, const void* src, int szbytes) {
  asm volatile("cp.async.cg.shared.global [%0], [%1], 16, %2;"
               :: "r"(dst), "l"(src), "r"(szbytes) : "memory");
}
#define CP_COMMIT() asm volatile("cp.async.commit_group;" ::: "memory")
#define CP_WAIT1()  asm volatile("cp.async.wait_group 1;" ::: "memory")
#define CP_WAIT0()  asm volatile("cp.async.wait_group 0;" ::: "memory")

__device__ __forceinline__ void mma16816(float* c, const uint32_t* a, const uint32_t* b) {
  asm volatile(
    "mma.sync.aligned.m16n8k16.row.col.f32.f16.f16.f32 "
    "{%0,%1,%2,%3}, {%4,%5,%6,%7}, {%8,%9}, {%0,%1,%2,%3};"
    : "+f"(c[0]), "+f"(c[1]), "+f"(c[2]), "+f"(c[3])
    : "r"(a[0]), "r"(a[1]), "r"(a[2]), "r"(a[3]), "r"(b[0]), "r"(b[1]));
}
#define LDSM_X4(r0, r1, r2, r3, addr) \
  asm volatile("ldmatrix.sync.aligned.m8n8.x4.shared.b16 {%0,%1,%2,%3}, [%4];" \
               : "=r"(r0), "=r"(r1), "=r"(r2), "=r"(r3) : "r"(addr))

// ---------------- K1: fused weight-convert + RMSNorm/split/flip ----------------
__global__ __launch_bounds__(256) void k_pre(
    const float* __restrict__ x, const float* __restrict__ norm_w,
    const float* __restrict__ s0, __half* __restrict__ d0, int n0,
    const float* __restrict__ s1, __half* __restrict__ d1, int n1,
    const float* __restrict__ s2, __half* __restrict__ d2, int n2,
    const float* __restrict__ s3, __half* __restrict__ d3, int n3,
    const float* __restrict__ s4, __half* __restrict__ d4, int n4)
{
  int tid = threadIdx.x;
  if (blockIdx.y < 5) {
    const float* s; __half* d; int n;
    switch (blockIdx.y) {
      case 0: s = s0; d = d0; n = n0; break;
      case 1: s = s1; d = d1; n = n1; break;
      case 2: s = s2; d = d2; n = n2; break;
      case 3: s = s3; d = d3; n = n3; break;
      default: s = s4; d = d4; n = n4; break;
    }
    int i = (blockIdx.x * 256 + tid) * 4;
    if (i < n) {
      float4 v = *(const float4*)(s + i);
      *(__half2*)(d + i)     = __floats2half2_rn(v.x, v.y);
      *(__half2*)(d + i + 2) = __floats2half2_rn(v.z, v.w);
    }
    return;
  }
  int row = blockIdx.x;
  const float* xr = x + (size_t)row * DMODEL;
  float v[4]; float ss = 0.f;
#pragma unroll
  for (int i = 0; i < 4; i++) { v[i] = xr[tid + i * 256]; ss += v[i] * v[i]; }
  __shared__ float red[256];
  red[tid] = ss; __syncthreads();
  for (int s = 128; s > 0; s >>= 1) { if (tid < s) red[tid] += red[tid + s]; __syncthreads(); }
  float scale = rsqrtf(red[0] * (1.f / DMODEL) + 1e-5f);
  int l = row & 2047, rrow = (row & ~2047) + (2047 - l);
#pragma unroll
  for (int i = 0; i < 4; i++) {
    int c = tid + i * 256;
    float val = v[i] * scale * norm_w[c];
    if (c < DHALF) g_uh[0][row][c] = __float2half(val);
    else           g_uh[1][rrow][c - DHALF] = __float2half(val);
  }
}

// ---------------- K2: fp16 GEMM, 2-stage, warp 64x64, TKS=64, z merges dirs ----------------
#define TKS    64
#define SROW   72
#define TILEH  (128 * SROW)
#define STAGEB (2 * TILEH * 2)
#define GSMEM  (2 * STAGEB)

__global__ __launch_bounds__(128)
void k_gemm_h(const __half* __restrict__ A, const __half* __restrict__ W,
              const float* __restrict__ bias, const float* __restrict__ res,
              float* __restrict__ Cf, __half* __restrict__ Ch,
              int Nw, int K, int ldc, int col_off, int colOffZ, int flipZ,
              size_t aStrideZ, size_t wStrideZ, size_t cStrideZ)
{
  extern __shared__ __half sm[];
  int z = blockIdx.z;
  A += (size_t)z * aStrideZ;
  W += (size_t)z * wStrideZ;
  if (Cf) Cf += (size_t)z * cStrideZ; else Ch += (size_t)z * cStrideZ;
  int coff = col_off + z * colOffZ;
  int flip = flipZ ? z : 0;

  int tid = threadIdx.x;
  int wid = tid >> 5, lane = tid & 31;
  int g = lane >> 2, tg = lane & 3;
  int wm = wid & 1, wn = wid >> 1;
  int row0 = blockIdx.y * 128, col0 = blockIdx.x * 128;

  uint32_t sbase = (uint32_t)__cvta_generic_to_shared(sm);

  int arow = lane & 15, acol = (lane >> 4) * 8;
  int brow = ((lane >> 4) & 1) * 8 + (lane & 7);
  int bcol = ((lane >> 3) & 1) * 8;

  float acc[4][8][4];
#pragma unroll
  for (int mi = 0; mi < 4; mi++)
#pragma unroll
    for (int ni = 0; ni < 8; ni++)
#pragma unroll
      for (int r = 0; r < 4; r++) acc[mi][ni][r] = 0.f;

  int KT = K / TKS;

#define LOAD_STAGE(stg, k0)                                                       \
  {                                                                               \
    uint32_t ab = sbase + (stg) * STAGEB;                                         \
    uint32_t bb = ab + TILEH * 2;                                                 \
    _Pragma("unroll")                                                             \
    for (int i = 0; i < 8; i++) {                                                 \
      int idx = tid + i * 128;                                                    \
      int r = idx >> 3, q = idx & 7;                                              \
      cp16(ab + (uint32_t)((r * SROW + q * 8) * 2),                               \
           A + (size_t)(row0 + r) * K + (k0) + q * 8, 16);                        \
      int wr = col0 + r;                                                          \
      const __half* ws = W + (size_t)(wr < Nw ? wr : 0) * K + (k0) + q * 8;       \
      cp16(bb + (uint32_t)((r * SROW + q * 8) * 2), ws, (wr < Nw) ? 16 : 0);      \
    }                                                                             \
    CP_COMMIT();                                                                  \
  }

  LOAD_STAGE(0, 0)

  for (int kt = 0; kt < KT; kt++) {
    int buf = kt & 1;
    if (kt + 1 < KT) {
      LOAD_STAGE(buf ^ 1, (kt + 1) * TKS)
      CP_WAIT1();
    } else {
      CP_WAIT0();
    }
    __syncthreads();

    uint32_t ab = sbase + (uint32_t)buf * STAGEB;
    uint32_t bb = ab + TILEH * 2;
#pragma unroll
    for (int kk = 0; kk < TKS; kk += 16) {
      uint32_t af[4][4], bf[8][2];
#pragma unroll
      for (int mi = 0; mi < 4; mi++) {
        uint32_t addr = ab + (uint32_t)(((wm * 64 + mi * 16 + arow) * SROW + kk + acol) * 2);
        LDSM_X4(af[mi][0], af[mi][1], af[mi][2], af[mi][3], addr);
      }
#pragma unroll
      for (int nb = 0; nb < 4; nb++) {
        uint32_t addr = bb + (uint32_t)(((wn * 64 + nb * 16 + brow) * SROW + kk + bcol) * 2);
        LDSM_X4(bf[nb * 2][0], bf[nb * 2][1], bf[nb * 2 + 1][0], bf[nb * 2 + 1][1], addr);
      }
#pragma unroll
      for (int mi = 0; mi < 4; mi++)
#pragma unroll
        for (int ni = 0; ni < 8; ni++)
          mma16816(acc[mi][ni], af[mi], bf[ni]);
    }
    __syncthreads();
  }

#pragma unroll
  for (int mi = 0; mi < 4; mi++) {
#pragma unroll
    for (int hf = 0; hf < 2; hf++) {
      int m = row0 + wm * 64 + mi * 16 + g + hf * 8;
      int orow = flip ? ((m & ~2047) + (2047 - (m & 2047))) : m;
      const float* rrow = res ? (res + (size_t)m * ldc + coff) : nullptr;
#pragma unroll
      for (int ni = 0; ni < 8; ni++) {
        int n = col0 + wn * 64 + ni * 8 + 2 * tg;
        if (n < Nw) {
          float v0 = acc[mi][ni][hf * 2 + 0];
          float v1 = acc[mi][ni][hf * 2 + 1];
          if (bias) { v0 += bias[n]; v1 += bias[n + 1]; }
          if (rrow) { v0 += rrow[n]; v1 += rrow[n + 1]; }
          if (Cf) {
            float* crow = Cf + (size_t)orow * ldc + coff;
            crow[n] = v0; crow[n + 1] = v1;
          } else {
            __half* crow = Ch + (size_t)orow * ldc + coff;
            crow[n] = __float2half(v0); crow[n + 1] = __float2half(v1);
          }
        }
      }
    }
  }
}

// ---------------- K3: conv(4)+SiLU via smem staging, softplus(dt), log-decay ----------------
__global__ __launch_bounds__(256) void k_conv(
    const float* __restrict__ cw0, const float* __restrict__ cb0,
    const float* __restrict__ db0, const float* __restrict__ al0,
    const float* __restrict__ cw1, const float* __restrict__ cb1,
    const float* __restrict__ db1, const float* __restrict__ al1)
{
  int dir = blockIdx.x >> 12;
  int row = blockIdx.x & 4095;
  int tid = threadIdx.x;
  const float* conv_w  = dir ? cw1 : cw0;
  const float* conv_b  = dir ? cb1 : cb0;
  const float* dt_bias = dir ? db1 : db0;
  const float* A_log   = dir ? al1 : al0;
  int l = row & 2047, rb = row & ~2047;

  __shared__ __half sxb[4][CONVDIM];
  const int VPR = CONVDIM / 8;
  for (int i = tid; i < 4 * VPR; i += 256) {
    int kr = i / VPR, off = (i - kr * VPR) * 8;
    int ls = l - 3 + kr;
    if (ls >= 0)
      *(uint4*)&sxb[kr][off] = *(const uint4*)&g_zxh[dir][rb + ls][DINNER + off];
  }
  __syncthreads();

  for (int c = tid; c < CONVDIM; c += 256) {
    float acc = conv_b[c];
#pragma unroll
    for (int k = 0; k < 4; k++) {
      int ls = l - 3 + k;
      if (ls >= 0) acc = fmaf(conv_w[c * 4 + k], __half2float(sxb[k][c]), acc);
    }
    g_xc[dir][row][c] = acc / (1.f + expf(-acc));
  }
  if (tid < NH) {
    float d = __half2float(g_zxh[dir][row][DINNER + CONVDIM + tid]) + dt_bias[tid];
    float sp = (d > 20.f) ? d : log1pf(expf(d));
    g_dt[dir][row][tid] = sp;
    g_ldA[dir][row][tid] = -sp * expf(A_log[tid]);
  }
}

// ================= SSD scan =================
#define A_BT   0                      // Bt[128][36]
#define A_CS   (A_BT + 128 * 36)      // Cs[32][132]
#define A_ST   (A_CS + 32 * 132)      // St[64][36]
#define A_W    (A_ST + 64 * 36)       // W [32][36]
#define A_LC   (A_W + 32 * 36)        // Lc[32]
#define A_ES   (A_LC + 32)            // es[32]
#define A_TOT  (A_ES + 32)
#define A_SMEM (A_TOT * 4)

__global__ __launch_bounds__(256, 2) void k_ssd_a()
{
  extern __shared__ float sms[];
  int c   = blockIdx.x;
  int dbh = blockIdx.y;
  int dir = dbh >> 5, b = (dbh >> 4) & 1, hh = dbh & 15;
  int rowbase = b * 2048 + c * CH;
  int tid = threadIdx.x;
  int w = tid >> 5, lane = tid & 31;

  // ---- load Bt, C, St, ldA ----
  for (int i = tid; i < CH * 32; i += 256) {
    int tt = i >> 5, c4 = i & 31;
    int row = rowbase + tt;
    float4 bv = *(const float4*)&g_xc[dir][row][DINNER + c4 * 4];
    float4 cv = *(const float4*)&g_xc[dir][row][DINNER + DSTATE + c4 * 4];
    *(float4*)&sms[A_CS + tt * 132 + c4 * 4] = cv;
    int n0 = c4 * 4;
    sms[A_BT + (n0 + 0) * 36 + tt] = bv.x;
    sms[A_BT + (n0 + 1) * 36 + tt] = bv.y;
    sms[A_BT + (n0 + 2) * 36 + tt] = bv.z;
    sms[A_BT + (n0 + 3) * 36 + tt] = bv.w;
  }
  for (int i = tid; i < CH * 16; i += 256) {
    int tt = i >> 4, q = i & 15;
    int row = rowbase + tt;
    float4 xv = *(const float4*)&g_xc[dir][row][hh * HD + q * 4];
    float dtv = g_dt[dir][row][hh];
    int p0 = q * 4;
    sms[A_ST + (p0 + 0) * 36 + tt] = dtv * xv.x;
    sms[A_ST + (p0 + 1) * 36 + tt] = dtv * xv.y;
    sms[A_ST + (p0 + 2) * 36 + tt] = dtv * xv.z;
    sms[A_ST + (p0 + 3) * 36 + tt] = dtv * xv.w;
  }
  if (tid < CH) sms[A_LC + tid] = g_ldA[dir][rowbase + tid][hh];
  __syncthreads();

  // ---- phase A: prefix Lc (tid0) + G = C·B^T ----
  if (tid == 0) {
    float L = 0.f;
    for (int s = 0; s < CH; s++) { L += sms[A_LC + s]; sms[A_LC + s] = L; }
  }
  {
    float gacc[4] = {0.f, 0.f, 0.f, 0.f};
    const float* c0r = &sms[A_CS + (w * 4 + 0) * 132];
    const float* c1r = &sms[A_CS + (w * 4 + 1) * 132];
    const float* c2r = &sms[A_CS + (w * 4 + 2) * 132];
    const float* c3r = &sms[A_CS + (w * 4 + 3) * 132];
#pragma unroll 8
    for (int n4 = 0; n4 < 32; n4++) {
      float4 c0 = *(const float4*)&c0r[n4 * 4];
      float4 c1 = *(const float4*)&c1r[n4 * 4];
      float4 c2 = *(const float4*)&c2r[n4 * 4];
      float4 c3 = *(const float4*)&c3r[n4 * 4];
      float b0 = sms[A_BT + (n4 * 4 + 0) * 36 + lane];
      float b1 = sms[A_BT + (n4 * 4 + 1) * 36 + lane];
      float b2 = sms[A_BT + (n4 * 4 + 2) * 36 + lane];
      float b3 = sms[A_BT + (n4 * 4 + 3) * 36 + lane];
      gacc[0] = fmaf(c0.x, b0, fmaf(c0.y, b1, fmaf(c0.z, b2, fmaf(c0.w, b3, gacc[0]))));
      gacc[1] = fmaf(c1.x, b0, fmaf(c1.y, b1, fmaf(c1.z, b2, fmaf(c1.w, b3, gacc[1]))));
      gacc[2] = fmaf(c2.x, b0, fmaf(c2.y, b1, fmaf(c2.z, b2, fmaf(c2.w, b3, gacc[2]))));
      gacc[3] = fmaf(c3.x, b0, fmaf(c3.y, b1, fmaf(c3.z, b2, fmaf(c3.w, b3, gacc[3]))));
    }
#pragma unroll
    for (int k = 0; k < 4; k++)
      sms[A_W + (w * 4 + k) * 36 + lane] = gacc[k];
  }
  __syncthreads();

  // ---- phase B: decay-mask W; es; et; lambda ----
#pragma unroll
  for (int k = 0; k < 4; k++) {
    int t = w * 4 + k;
    float wv = sms[A_W + t * 36 + lane];
    float m = (lane <= t) ? expf(sms[A_LC + t] - sms[A_LC + lane]) : 0.f;
    sms[A_W + t * 36 + lane] = wv * m;
  }
  if (tid < CH) {
    sms[A_ES + tid] = expf(sms[A_LC + CH - 1] - sms[A_LC + tid]);
    g_et[dbh][c][tid] = expf(sms[A_LC + tid]);
  }
  if (tid == 0) g_lam[dbh][c] = expf(sms[A_LC + CH - 1]);
  __syncthreads();

  // ---- phase C: Y_intra = W @ S ----
  {
    float y0[4] = {0.f, 0.f, 0.f, 0.f};
    float y1[4] = {0.f, 0.f, 0.f, 0.f};
#pragma unroll
    for (int s4 = 0; s4 < 8; s4++) {
      float4 sa = *(const float4*)&sms[A_ST + lane * 36 + s4 * 4];
      float4 sb = *(const float4*)&sms[A_ST + (lane + 32) * 36 + s4 * 4];
#pragma unroll
      for (int k = 0; k < 4; k++) {
        float4 wv = *(const float4*)&sms[A_W + (w * 4 + k) * 36 + s4 * 4];
        y0[k] = fmaf(wv.x, sa.x, fmaf(wv.y, sa.y, fmaf(wv.z, sa.z, fmaf(wv.w, sa.w, y0[k]))));
        y1[k] = fmaf(wv.x, sb.x, fmaf(wv.y, sb.y, fmaf(wv.z, sb.z, fmaf(wv.w, sb.w, y1[k]))));
      }
    }
#pragma unroll
    for (int k = 0; k < 4; k++) {
      int row = rowbase + w * 4 + k;
      g_y[dir][row][hh * HD + lane]      = y0[k];
      g_y[dir][row][hh * HD + lane + 32] = y1[k];
    }
  }

  // ---- phase D: U[p][n] = sum_s (es[s]*S[s][p]) * B[s][n], two 4p-passes ----
#pragma unroll
  for (int half = 0; half < 2; half++) {
    int p0 = w * 8 + half * 4;
    float u[4][4];
#pragma unroll
    for (int pk = 0; pk < 4; pk++)
#pragma unroll
      for (int nk = 0; nk < 4; nk++) u[pk][nk] = 0.f;
#pragma unroll
    for (int s4 = 0; s4 < 8; s4++) {
      float4 ev = *(const float4*)&sms[A_ES + s4 * 4];
      float4 sa[4];
#pragma unroll
      for (int pk = 0; pk < 4; pk++) {
        sa[pk] = *(const float4*)&sms[A_ST + (p0 + pk) * 36 + s4 * 4];
        sa[pk].x *= ev.x; sa[pk].y *= ev.y; sa[pk].z *= ev.z; sa[pk].w *= ev.w;
      }
#pragma unroll
      for (int nk = 0; nk < 4; nk++) {
        float4 bt = *(const float4*)&sms[A_BT + (lane + nk * 32) * 36 + s4 * 4];
#pragma unroll
        for (int pk = 0; pk < 4; pk++)
          u[pk][nk] = fmaf(bt.x, sa[pk].x, fmaf(bt.y, sa[pk].y,
                      fmaf(bt.z, sa[pk].z, fmaf(bt.w, sa[pk].w, u[pk][nk]))));
      }
    }
#pragma unroll
    for (int pk = 0; pk < 4; pk++)
#pragma unroll
      for (int nk = 0; nk < 4; nk++)
        g_U[dbh][c][p0 + pk][lane + nk * 32] = u[pk][nk];
  }
}

// ---- fused chunk recurrence + Y_state: 128 blocks (dbh x p-half) ----
__global__ __launch_bounds__(256) void k_ssd_bd(const float* __restrict__ Df,
                                                const float* __restrict__ Db)
{
  __shared__ float sh[32][132];   // h[pr][n], state carried across chunks
  __shared__ float sc[32][132];   // C[t][n]
  __shared__ float set[CH];
  int bx = blockIdx.x;            // 128 = dbh*2 + ph
  int dbh = bx >> 1, ph = bx & 1;
  int dir = dbh >> 5, b = (dbh >> 4) & 1, hh = dbh & 15;
  int tid = threadIdx.x, w = tid >> 5, lane = tid & 31;
  float Dh = (dir ? Db : Df)[hh];
  int pg0 = ph * 32;

  float* shf = &sh[0][0];
  for (int i = tid; i < 32 * 132; i += 256) shf[i] = 0.f;
  __syncthreads();

  for (int c = 0; c < NCH; c++) {
    int rowbase = b * 2048 + c * CH;
    for (int i = tid; i < CH * 32; i += 256) {
      int t = i >> 5, q = i & 31;
      *(float4*)&sc[t][q * 4] =
          *(const float4*)&g_xc[dir][rowbase + t][DINNER + DSTATE + q * 4];
    }
    if (tid < CH) set[tid] = g_et[dbh][c][tid];
    float lam = g_lam[dbh][c];
    __syncthreads();

    // Y_state: warp w -> t rows w*4..+3, lane -> pr
    float a[4] = {0.f, 0.f, 0.f, 0.f};
#pragma unroll 8
    for (int n4 = 0; n4 < 32; n4++) {
      float4 hv = *(const float4*)&sh[lane][n4 * 4];
#pragma unroll
      for (int k = 0; k < 4; k++) {
        float4 cv = *(const float4*)&sc[w * 4 + k][n4 * 4];
        a[k] = fmaf(cv.x, hv.x, fmaf(cv.y, hv.y, fmaf(cv.z, hv.z, fmaf(cv.w, hv.w, a[k]))));
      }
    }
#pragma unroll
    for (int k = 0; k < 4; k++) {
      int t = w * 4 + k;
      int row = rowbase + t;
      int col = hh * HD + pg0 + lane;
      float x = g_xc[dir][row][col];
      g_y[dir][row][col] = g_y[dir][row][col] + set[t] * a[k] + Dh * x;
    }
    __syncthreads();

    // h update: h = lam*h + U[p][n]
    {
      int pr = tid >> 3, no = (tid & 7) * 16;
      const float* Up = &g_U[dbh][c][pg0 + pr][no];
#pragma unroll
      for (int q = 0; q < 4; q++) {
        float4 hv = *(float4*)&sh[pr][no + q * 4];
        float4 uv = *(const float4*)&Up[q * 4];
        hv.x = fmaf(lam, hv.x, uv.x);
        hv.y = fmaf(lam, hv.y, uv.y);
        hv.z = fmaf(lam, hv.z, uv.z);
        hv.w = fmaf(lam, hv.w, uv.w);
        *(float4*)&sh[pr][no + q * 4] = hv;
      }
    }
    __syncthreads();
  }
}

// ---------------- K5: gating + gated RMSNorm -> fp16, both dirs ----------------
__global__ __launch_bounds__(256) void k_gate(const float* __restrict__ gw0,
                                              const float* __restrict__ gw1)
{
  int dir = blockIdx.x >> 12;
  int row = blockIdx.x & 4095;
  int tid = threadIdx.x;
  const float* gnorm_w = dir ? gw1 : gw0;
  float vals[4]; float ss = 0.f;
#pragma unroll
  for (int i = 0; i < 4; i++) {
    int c = tid + i * 256;
    float yv = g_y[dir][row][c];
    float z = __half2float(g_zxh[dir][row][c]);
    float gv = yv * (z / (1.f + expf(-z)));
    vals[i] = gv; ss += gv * gv;
  }
  __shared__ float red[256];
  red[tid] = ss; __syncthreads();
  for (int s = 128; s > 0; s >>= 1) { if (tid < s) red[tid] += red[tid + s]; __syncthreads(); }
  float sc = rsqrtf(red[0] * (1.f / DINNER) + 1e-5f);
#pragma unroll
  for (int i = 0; i < 4; i++) {
    int c = tid + i * 256;
    g_yh[dir][row][c] = __float2half(vals[i] * sc * gnorm_w[c]);
  }
}

// ---------------- launch ----------------
extern "C" void kernel_launch(void* const* d_in, const int* in_sizes, int n_in,
                              void* d_out, int out_size)
{
  (void)in_sizes; (void)n_in; (void)out_size;
  const float* x      = (const float*)d_in[0];
  const float* norm_w = (const float*)d_in[1];
  const float* op_w   = (const float*)d_in[2];
  const float* op_b   = (const float*)d_in[3];
  const float* in_w[2]    = {(const float*)d_in[4],  (const float*)d_in[12]};
  const float* conv_w[2]  = {(const float*)d_in[5],  (const float*)d_in[13]};
  const float* conv_b[2]  = {(const float*)d_in[6],  (const float*)d_in[14]};
  const float* dt_bias[2] = {(const float*)d_in[7],  (const float*)d_in[15]};
  const float* A_log[2]   = {(const float*)d_in[8],  (const float*)d_in[16]};
  const float* Dvec[2]    = {(const float*)d_in[9],  (const float*)d_in[17]};
  const float* gnorm[2]   = {(const float*)d_in[10], (const float*)d_in[18]};
  const float* outp_w[2]  = {(const float*)d_in[11], (const float*)d_in[19]};
  float* out = (float*)d_out;

  __half *pwi, *pwo, *pwp, *puh, *pyh, *podh, *pzxh;
  cudaGetSymbolAddress((void**)&pwi, wh_in);
  cudaGetSymbolAddress((void**)&pwo, wh_out);
  cudaGetSymbolAddress((void**)&pwp, wh_op);
  cudaGetSymbolAddress((void**)&puh, g_uh);
  cudaGetSymbolAddress((void**)&pyh, g_yh);
  cudaGetSymbolAddress((void**)&podh, g_odh);
  cudaGetSymbolAddress((void**)&pzxh, g_zxh);

  static int attr_set = 0;
  if (!attr_set) {
    cudaFuncSetAttribute(k_gemm_h, cudaFuncAttributeMaxDynamicSharedMemorySize, GSMEM);
    cudaFuncSetAttribute(k_ssd_a,  cudaFuncAttributeMaxDynamicSharedMemorySize, A_SMEM);
    attr_set = 1;
  }

  // 1: weight convert + rmsnorm (fused)
  k_pre<<<dim3(BL, 6), 256>>>(
      x, norm_w,
      in_w[0],   pwi,                  DPROJ * DHALF,
      in_w[1],   pwi + DPROJ * DHALF,  DPROJ * DHALF,
      outp_w[0], pwo,                  DHALF * DINNER,
      outp_w[1], pwo + DHALF * DINNER, DHALF * DINNER,
      op_w,      pwp,                  DMODEL * DMODEL);

  // 2: in-proj, both dirs, fp16 output
  k_gemm_h<<<dim3((DPROJ + 127) / 128, BL / 128, 2), 128, GSMEM>>>(
      puh, pwi, nullptr, nullptr, nullptr, pzxh,
      DPROJ, DHALF, DPROJ, 0, 0, 0,
      (size_t)BL * DHALF, (size_t)DPROJ * DHALF, (size_t)BL * DPROJ);

  // 3: conv
  k_conv<<<2 * BL, 256>>>(conv_w[0], conv_b[0], dt_bias[0], A_log[0],
                          conv_w[1], conv_b[1], dt_bias[1], A_log[1]);

  // 4-5: chunked-SSD scan (fused recurrence)
  k_ssd_a<<<dim3(NCH, DBH), 256, A_SMEM>>>();
  k_ssd_bd<<<DBH * 2, 256>>>(Dvec[0], Dvec[1]);

  // 6: gate
  k_gate<<<2 * BL, 256>>>(gnorm[0], gnorm[1]);

  // 7: out-proj, both dirs
  k_gemm_h<<<dim3(DHALF / 128, BL / 128, 2), 128, GSMEM>>>(
      pyh, pwo, nullptr, nullptr, nullptr, podh,
      DHALF, DINNER, DMODEL, 0, DHALF, 1,
      (size_t)BL * DINNER, (size_t)DHALF * DINNER, 0);

  // 8: final projection (+bias, +residual x)
  k_gemm_h<<<dim3(DMODEL / 128, BL / 128, 1), 128, GSMEM>>>(
      podh, pwp, op_b, x, out, nullptr,
      DMODEL, DMODEL, DMODEL, 0, 0, 0, 0, 0, 0);
}

// round 17
// speedup vs baseline: 1.4657x; 1.4657x over previous
#include <cuda_runtime.h>
#include <cuda_fp16.h>
#include <cstdint>
#include <cstddef>

#define BATCH   2
#define LSEQ    2048
#define BL      4096
#define DMODEL  1024
#define DHALF   512
#define DINNER  1024
#define DSTATE  128
#define NH      16
#define HD      64
#define CONVDIM 1280
#define DPROJ   2320
#define CH      32
#define NCH     (LSEQ / CH)
#define DBH     64

// ---------------- scratch ----------------
__device__ __half g_uh[2][BL][DHALF];
__device__ __half g_zxh[2][BL][DPROJ];
__device__ float  g_xc[2][BL][CONVDIM];
__device__ float  g_dt[2][BL][NH];
__device__ float  g_ldA[2][BL][NH];
__device__ float  g_y[2][BL][DINNER];
__device__ __half g_yh[2][BL][DINNER];
__device__ __half g_odh[BL][DMODEL];
__device__ __half wh_in[2][DPROJ * DHALF];
__device__ __half wh_out[2][DHALF * DINNER];
__device__ __half wh_op[DMODEL * DMODEL];
__device__ float  g_U[DBH][NCH][HD][DSTATE];    // [p][n]
__device__ float  g_hst[DBH][NCH][HD][DSTATE];  // [p][n]
__device__ float  g_lam[DBH][NCH];
__device__ float  g_et[DBH][NCH][CH];

// ---------------- helpers ----------------
__device__ __forceinline__ void cp16(uint32_t dst, const void* src, int szbytes) {
  asm volatile("cp.async.cg.shared.global [%0], [%1], 16, %2;"
               :: "r"(dst), "l"(src), "r"(szbytes) : "memory");
}
#define CP_COMMIT() asm volatile("cp.async.commit_group;" ::: "memory")
#define CP_WAIT1()  asm volatile("cp.async.wait_group 1;" ::: "memory")
#define CP_WAIT0()  asm volatile("cp.async.wait_group 0;" ::: "memory")

__device__ __forceinline__ void mma16816(float* c, const uint32_t* a, const uint32_t* b) {
  asm volatile(
    "mma.sync.aligned.m16n8k16.row.col.f32.f16.f16.f32 "
    "{%0,%1,%2,%3}, {%4,%5,%6,%7}, {%8,%9}, {%0,%1,%2,%3};"
    : "+f"(c[0]), "+f"(c[1]), "+f"(c[2]), "+f"(c[3])
    : "r"(a[0]), "r"(a[1]), "r"(a[2]), "r"(a[3]), "r"(b[0]), "r"(b[1]));
}
#define LDSM_X4(r0, r1, r2, r3, addr) \
  asm volatile("ldmatrix.sync.aligned.m8n8.x4.shared.b16 {%0,%1,%2,%3}, [%4];" \
               : "=r"(r0), "=r"(r1), "=r"(r2), "=r"(r3) : "r"(addr))

// ---------------- K1: fused weight-convert + RMSNorm/split/flip ----------------
__global__ __launch_bounds__(256) void k_pre(
    const float* __restrict__ x, const float* __restrict__ norm_w,
    const float* __restrict__ s0, __half* __restrict__ d0, int n0,
    const float* __restrict__ s1, __half* __restrict__ d1, int n1,
    const float* __restrict__ s2, __half* __restrict__ d2, int n2,
    const float* __restrict__ s3, __half* __restrict__ d3, int n3,
    const float* __restrict__ s4, __half* __restrict__ d4, int n4)
{
  int tid = threadIdx.x;
  if (blockIdx.y < 5) {
    const float* s; __half* d; int n;
    switch (blockIdx.y) {
      case 0: s = s0; d = d0; n = n0; break;
      case 1: s = s1; d = d1; n = n1; break;
      case 2: s = s2; d = d2; n = n2; break;
      case 3: s = s3; d = d3; n = n3; break;
      default: s = s4; d = d4; n = n4; break;
    }
    int i = (blockIdx.x * 256 + tid) * 4;
    if (i < n) {
      float4 v = *(const float4*)(s + i);
      *(__half2*)(d + i)     = __floats2half2_rn(v.x, v.y);
      *(__half2*)(d + i + 2) = __floats2half2_rn(v.z, v.w);
    }
    return;
  }
  int row = blockIdx.x;
  const float* xr = x + (size_t)row * DMODEL;
  float v[4]; float ss = 0.f;
#pragma unroll
  for (int i = 0; i < 4; i++) { v[i] = xr[tid + i * 256]; ss += v[i] * v[i]; }
  __shared__ float red[256];
  red[tid] = ss; __syncthreads();
  for (int s = 128; s > 0; s >>= 1) { if (tid < s) red[tid] += red[tid + s]; __syncthreads(); }
  float scale = rsqrtf(red[0] * (1.f / DMODEL) + 1e-5f);
  int l = row & 2047, rrow = (row & ~2047) + (2047 - l);
#pragma unroll
  for (int i = 0; i < 4; i++) {
    int c = tid + i * 256;
    float val = v[i] * scale * norm_w[c];
    if (c < DHALF) g_uh[0][row][c] = __float2half(val);
    else           g_uh[1][rrow][c - DHALF] = __float2half(val);
  }
}

// ---------------- K2: fp16 GEMM, 2-stage, warp 64x64, TKS=64, z merges dirs ----------------
#define TKS    64
#define SROW   72
#define TILEH  (128 * SROW)
#define STAGEB (2 * TILEH * 2)
#define GSMEM  (2 * STAGEB)

__global__ __launch_bounds__(128)
void k_gemm_h(const __half* __restrict__ A, const __half* __restrict__ W,
              const float* __restrict__ bias, const float* __restrict__ res,
              float* __restrict__ Cf, __half* __restrict__ Ch,
              int Nw, int K, int ldc, int col_off, int colOffZ, int flipZ,
              size_t aStrideZ, size_t wStrideZ, size_t cStrideZ)
{
  extern __shared__ __half sm[];
  int z = blockIdx.z;
  A += (size_t)z * aStrideZ;
  W += (size_t)z * wStrideZ;
  if (Cf) Cf += (size_t)z * cStrideZ; else Ch += (size_t)z * cStrideZ;
  int coff = col_off + z * colOffZ;
  int flip = flipZ ? z : 0;

  int tid = threadIdx.x;
  int wid = tid >> 5, lane = tid & 31;
  int g = lane >> 2, tg = lane & 3;
  int wm = wid & 1, wn = wid >> 1;
  int row0 = blockIdx.y * 128, col0 = blockIdx.x * 128;

  uint32_t sbase = (uint32_t)__cvta_generic_to_shared(sm);

  int arow = lane & 15, acol = (lane >> 4) * 8;
  int brow = ((lane >> 4) & 1) * 8 + (lane & 7);
  int bcol = ((lane >> 3) & 1) * 8;

  float acc[4][8][4];
#pragma unroll
  for (int mi = 0; mi < 4; mi++)
#pragma unroll
    for (int ni = 0; ni < 8; ni++)
#pragma unroll
      for (int r = 0; r < 4; r++) acc[mi][ni][r] = 0.f;

  int KT = K / TKS;

#define LOAD_STAGE(stg, k0)                                                       \
  {                                                                               \
    uint32_t ab = sbase + (stg) * STAGEB;                                         \
    uint32_t bb = ab + TILEH * 2;                                                 \
    _Pragma("unroll")                                                             \
    for (int i = 0; i < 8; i++) {                                                 \
      int idx = tid + i * 128;                                                    \
      int r = idx >> 3, q = idx & 7;                                              \
      cp16(ab + (uint32_t)((r * SROW + q * 8) * 2),                               \
           A + (size_t)(row0 + r) * K + (k0) + q * 8, 16);                        \
      int wr = col0 + r;                                                          \
      const __half* ws = W + (size_t)(wr < Nw ? wr : 0) * K + (k0) + q * 8;       \
      cp16(bb + (uint32_t)((r * SROW + q * 8) * 2), ws, (wr < Nw) ? 16 : 0);      \
    }                                                                             \
    CP_COMMIT();                                                                  \
  }

  LOAD_STAGE(0, 0)

  for (int kt = 0; kt < KT; kt++) {
    int buf = kt & 1;
    if (kt + 1 < KT) {
      LOAD_STAGE(buf ^ 1, (kt + 1) * TKS)
      CP_WAIT1();
    } else {
      CP_WAIT0();
    }
    __syncthreads();

    uint32_t ab = sbase + (uint32_t)buf * STAGEB;
    uint32_t bb = ab + TILEH * 2;
#pragma unroll
    for (int kk = 0; kk < TKS; kk += 16) {
      uint32_t af[4][4], bf[8][2];
#pragma unroll
      for (int mi = 0; mi < 4; mi++) {
        uint32_t addr = ab + (uint32_t)(((wm * 64 + mi * 16 + arow) * SROW + kk + acol) * 2);
        LDSM_X4(af[mi][0], af[mi][1], af[mi][2], af[mi][3], addr);
      }
#pragma unroll
      for (int nb = 0; nb < 4; nb++) {
        uint32_t addr = bb + (uint32_t)(((wn * 64 + nb * 16 + brow) * SROW + kk + bcol) * 2);
        LDSM_X4(bf[nb * 2][0], bf[nb * 2][1], bf[nb * 2 + 1][0], bf[nb * 2 + 1][1], addr);
      }
#pragma unroll
      for (int mi = 0; mi < 4; mi++)
#pragma unroll
        for (int ni = 0; ni < 8; ni++)
          mma16816(acc[mi][ni], af[mi], bf[ni]);
    }
    __syncthreads();
  }

#pragma unroll
  for (int mi = 0; mi < 4; mi++) {
#pragma unroll
    for (int hf = 0; hf < 2; hf++) {
      int m = row0 + wm * 64 + mi * 16 + g + hf * 8;
      int orow = flip ? ((m & ~2047) + (2047 - (m & 2047))) : m;
      const float* rrow = res ? (res + (size_t)m * ldc + coff) : nullptr;
#pragma unroll
      for (int ni = 0; ni < 8; ni++) {
        int n = col0 + wn * 64 + ni * 8 + 2 * tg;
        if (n < Nw) {
          float v0 = acc[mi][ni][hf * 2 + 0];
          float v1 = acc[mi][ni][hf * 2 + 1];
          if (bias) { v0 += bias[n]; v1 += bias[n + 1]; }
          if (rrow) { v0 += rrow[n]; v1 += rrow[n + 1]; }
          if (Cf) {
            float* crow = Cf + (size_t)orow * ldc + coff;
            crow[n] = v0; crow[n + 1] = v1;
          } else {
            __half* crow = Ch + (size_t)orow * ldc + coff;
            crow[n] = __float2half(v0); crow[n + 1] = __float2half(v1);
          }
        }
      }
    }
  }
}

// ---------------- K3: conv(4)+SiLU via smem staging, softplus(dt), log-decay ----------------
__global__ __launch_bounds__(256) void k_conv(
    const float* __restrict__ cw0, const float* __restrict__ cb0,
    const float* __restrict__ db0, const float* __restrict__ al0,
    const float* __restrict__ cw1, const float* __restrict__ cb1,
    const float* __restrict__ db1, const float* __restrict__ al1)
{
  int dir = blockIdx.x >> 12;
  int row = blockIdx.x & 4095;
  int tid = threadIdx.x;
  const float* conv_w  = dir ? cw1 : cw0;
  const float* conv_b  = dir ? cb1 : cb0;
  const float* dt_bias = dir ? db1 : db0;
  const float* A_log   = dir ? al1 : al0;
  int l = row & 2047, rb = row & ~2047;

  __shared__ __half sxb[4][CONVDIM];
  const int VPR = CONVDIM / 8;
  for (int i = tid; i < 4 * VPR; i += 256) {
    int kr = i / VPR, off = (i - kr * VPR) * 8;
    int ls = l - 3 + kr;
    if (ls >= 0)
      *(uint4*)&sxb[kr][off] = *(const uint4*)&g_zxh[dir][rb + ls][DINNER + off];
  }
  __syncthreads();

  for (int c = tid; c < CONVDIM; c += 256) {
    float acc = conv_b[c];
#pragma unroll
    for (int k = 0; k < 4; k++) {
      int ls = l - 3 + k;
      if (ls >= 0) acc = fmaf(conv_w[c * 4 + k], __half2float(sxb[k][c]), acc);
    }
    g_xc[dir][row][c] = acc / (1.f + expf(-acc));
  }
  if (tid < NH) {
    float d = __half2float(g_zxh[dir][row][DINNER + CONVDIM + tid]) + dt_bias[tid];
    float sp = (d > 20.f) ? d : log1pf(expf(d));
    g_dt[dir][row][tid] = sp;
    g_ldA[dir][row][tid] = -sp * expf(A_log[tid]);
  }
}

// ================= SSD scan =================
#define A_BT   0                      // Bt[128][36]
#define A_CS   (A_BT + 128 * 36)      // Cs[32][132]
#define A_ST   (A_CS + 32 * 132)      // St[64][36]
#define A_W    (A_ST + 64 * 36)       // W [32][36]
#define A_LC   (A_W + 32 * 36)        // Lc[32]
#define A_ES   (A_LC + 32)            // es[32]
#define A_TOT  (A_ES + 32)
#define A_SMEM (A_TOT * 4)

__global__ __launch_bounds__(256, 2) void k_ssd_a()
{
  extern __shared__ float sms[];
  int c   = blockIdx.x;
  int dbh = blockIdx.y;
  int dir = dbh >> 5, b = (dbh >> 4) & 1, hh = dbh & 15;
  int rowbase = b * 2048 + c * CH;
  int tid = threadIdx.x;
  int w = tid >> 5, lane = tid & 31;

  for (int i = tid; i < CH * 32; i += 256) {
    int tt = i >> 5, c4 = i & 31;
    int row = rowbase + tt;
    float4 bv = *(const float4*)&g_xc[dir][row][DINNER + c4 * 4];
    float4 cv = *(const float4*)&g_xc[dir][row][DINNER + DSTATE + c4 * 4];
    *(float4*)&sms[A_CS + tt * 132 + c4 * 4] = cv;
    int n0 = c4 * 4;
    sms[A_BT + (n0 + 0) * 36 + tt] = bv.x;
    sms[A_BT + (n0 + 1) * 36 + tt] = bv.y;
    sms[A_BT + (n0 + 2) * 36 + tt] = bv.z;
    sms[A_BT + (n0 + 3) * 36 + tt] = bv.w;
  }
  for (int i = tid; i < CH * 16; i += 256) {
    int tt = i >> 4, q = i & 15;
    int row = rowbase + tt;
    float4 xv = *(const float4*)&g_xc[dir][row][hh * HD + q * 4];
    float dtv = g_dt[dir][row][hh];
    int p0 = q * 4;
    sms[A_ST + (p0 + 0) * 36 + tt] = dtv * xv.x;
    sms[A_ST + (p0 + 1) * 36 + tt] = dtv * xv.y;
    sms[A_ST + (p0 + 2) * 36 + tt] = dtv * xv.z;
    sms[A_ST + (p0 + 3) * 36 + tt] = dtv * xv.w;
  }
  if (tid < CH) sms[A_LC + tid] = g_ldA[dir][rowbase + tid][hh];
  __syncthreads();

  if (tid == 0) {
    float L = 0.f;
    for (int s = 0; s < CH; s++) { L += sms[A_LC + s]; sms[A_LC + s] = L; }
  }
  {
    float gacc[4] = {0.f, 0.f, 0.f, 0.f};
    const float* c0r = &sms[A_CS + (w * 4 + 0) * 132];
    const float* c1r = &sms[A_CS + (w * 4 + 1) * 132];
    const float* c2r = &sms[A_CS + (w * 4 + 2) * 132];
    const float* c3r = &sms[A_CS + (w * 4 + 3) * 132];
#pragma unroll 8
    for (int n4 = 0; n4 < 32; n4++) {
      float4 c0 = *(const float4*)&c0r[n4 * 4];
      float4 c1 = *(const float4*)&c1r[n4 * 4];
      float4 c2 = *(const float4*)&c2r[n4 * 4];
      float4 c3 = *(const float4*)&c3r[n4 * 4];
      float b0 = sms[A_BT + (n4 * 4 + 0) * 36 + lane];
      float b1 = sms[A_BT + (n4 * 4 + 1) * 36 + lane];
      float b2 = sms[A_BT + (n4 * 4 + 2) * 36 + lane];
      float b3 = sms[A_BT + (n4 * 4 + 3) * 36 + lane];
      gacc[0] = fmaf(c0.x, b0, fmaf(c0.y, b1, fmaf(c0.z, b2, fmaf(c0.w, b3, gacc[0]))));
      gacc[1] = fmaf(c1.x, b0, fmaf(c1.y, b1, fmaf(c1.z, b2, fmaf(c1.w, b3, gacc[1]))));
      gacc[2] = fmaf(c2.x, b0, fmaf(c2.y, b1, fmaf(c2.z, b2, fmaf(c2.w, b3, gacc[2]))));
      gacc[3] = fmaf(c3.x, b0, fmaf(c3.y, b1, fmaf(c3.z, b2, fmaf(c3.w, b3, gacc[3]))));
    }
#pragma unroll
    for (int k = 0; k < 4; k++)
      sms[A_W + (w * 4 + k) * 36 + lane] = gacc[k];
  }
  __syncthreads();

#pragma unroll
  for (int k = 0; k < 4; k++) {
    int t = w * 4 + k;
    float wv = sms[A_W + t * 36 + lane];
    float m = (lane <= t) ? expf(sms[A_LC + t] - sms[A_LC + lane]) : 0.f;
    sms[A_W + t * 36 + lane] = wv * m;
  }
  if (tid < CH) {
    sms[A_ES + tid] = expf(sms[A_LC + CH - 1] - sms[A_LC + tid]);
    g_et[dbh][c][tid] = expf(sms[A_LC + tid]);
  }
  if (tid == 0) g_lam[dbh][c] = expf(sms[A_LC + CH - 1]);
  __syncthreads();

  {
    float y0[4] = {0.f, 0.f, 0.f, 0.f};
    float y1[4] = {0.f, 0.f, 0.f, 0.f};
#pragma unroll
    for (int s4 = 0; s4 < 8; s4++) {
      float4 sa = *(const float4*)&sms[A_ST + lane * 36 + s4 * 4];
      float4 sb = *(const float4*)&sms[A_ST + (lane + 32) * 36 + s4 * 4];
#pragma unroll
      for (int k = 0; k < 4; k++) {
        float4 wv = *(const float4*)&sms[A_W + (w * 4 + k) * 36 + s4 * 4];
        y0[k] = fmaf(wv.x, sa.x, fmaf(wv.y, sa.y, fmaf(wv.z, sa.z, fmaf(wv.w, sa.w, y0[k]))));
        y1[k] = fmaf(wv.x, sb.x, fmaf(wv.y, sb.y, fmaf(wv.z, sb.z, fmaf(wv.w, sb.w, y1[k]))));
      }
    }
#pragma unroll
    for (int k = 0; k < 4; k++) {
      int row = rowbase + w * 4 + k;
      g_y[dir][row][hh * HD + lane]      = y0[k];
      g_y[dir][row][hh * HD + lane + 32] = y1[k];
    }
  }

#pragma unroll
  for (int half = 0; half < 2; half++) {
    int p0 = w * 8 + half * 4;
    float u[4][4];
#pragma unroll
    for (int pk = 0; pk < 4; pk++)
#pragma unroll
      for (int nk = 0; nk < 4; nk++) u[pk][nk] = 0.f;
#pragma unroll
    for (int s4 = 0; s4 < 8; s4++) {
      float4 ev = *(const float4*)&sms[A_ES + s4 * 4];
      float4 sa[4];
#pragma unroll
      for (int pk = 0; pk < 4; pk++) {
        sa[pk] = *(const float4*)&sms[A_ST + (p0 + pk) * 36 + s4 * 4];
        sa[pk].x *= ev.x; sa[pk].y *= ev.y; sa[pk].z *= ev.z; sa[pk].w *= ev.w;
      }
#pragma unroll
      for (int nk = 0; nk < 4; nk++) {
        float4 bt = *(const float4*)&sms[A_BT + (lane + nk * 32) * 36 + s4 * 4];
#pragma unroll
        for (int pk = 0; pk < 4; pk++)
          u[pk][nk] = fmaf(bt.x, sa[pk].x, fmaf(bt.y, sa[pk].y,
                      fmaf(bt.z, sa[pk].z, fmaf(bt.w, sa[pk].w, u[pk][nk]))));
      }
    }
#pragma unroll
    for (int pk = 0; pk < 4; pk++)
#pragma unroll
      for (int nk = 0; nk < 4; nk++)
        g_U[dbh][c][p0 + pk][lane + nk * 32] = u[pk][nk];
  }
}

// ---- K_c: chunk recurrence on [p][n], prefetched ----
__global__ __launch_bounds__(256) void k_ssd_rec()
{
  __shared__ float lam_s[NCH];
  int bx = blockIdx.x;                 // DBH*32 blocks
  int dbh = bx >> 5, sl = bx & 31;
  int tid = threadIdx.x;
  if (tid < NCH) lam_s[tid] = g_lam[dbh][tid];
  __syncthreads();
  int slot = sl * 256 + tid;           // 0..8191
  int p = slot >> 7, n = slot & 127;
  float h = 0.f;
  float nextU = g_U[dbh][0][p][n];
  for (int c = 0; c < NCH; c++) {
    float Uc = nextU;
    if (c + 1 < NCH) nextU = g_U[dbh][c + 1][p][n];
    g_hst[dbh][c][p][n] = h;
    h = fmaf(lam_s[c], h, Uc);
  }
}

// ---- K_d: Y_state + combine (h already [p][n]) ----
#define D_HT   0                       // ht[64][132]
#define D_CS   (D_HT + 64 * 132)       // Cs[32][132]
#define D_ET   (D_CS + 32 * 132)       // et[32]
#define D_TOT  (D_ET + 32)
#define D_SMEM (D_TOT * 4)

__global__ __launch_bounds__(256) void k_ssd_d(const float* __restrict__ Df,
                                               const float* __restrict__ Db)
{
  extern __shared__ float sms[];
  int c   = blockIdx.x;
  int dbh = blockIdx.y;
  int dir = dbh >> 5, b = (dbh >> 4) & 1, hh = dbh & 15;
  int rowbase = b * 2048 + c * CH;
  int tid = threadIdx.x;
  int w = tid >> 5, lane = tid & 31;
  float Dh = (dir ? Db : Df)[hh];

  for (int i = tid; i < HD * 32; i += 256) {       // h [p][n] direct float4
    int p = i >> 5, q = i & 31;
    *(float4*)&sms[D_HT + p * 132 + q * 4] = *(const float4*)&g_hst[dbh][c][p][q * 4];
  }
  for (int i = tid; i < CH * 32; i += 256) {
    int tt = i >> 5, c4 = i & 31;
    *(float4*)&sms[D_CS + tt * 132 + c4 * 4] =
        *(const float4*)&g_xc[dir][rowbase + tt][DINNER + DSTATE + c4 * 4];
  }
  if (tid < CH) sms[D_ET + tid] = g_et[dbh][c][tid];
  __syncthreads();

  float a0[4] = {0.f, 0.f, 0.f, 0.f};
  float a1[4] = {0.f, 0.f, 0.f, 0.f};
#pragma unroll 8
  for (int n4 = 0; n4 < 32; n4++) {
    float4 ha = *(const float4*)&sms[D_HT + lane * 132 + n4 * 4];
    float4 hb = *(const float4*)&sms[D_HT + (lane + 32) * 132 + n4 * 4];
#pragma unroll
    for (int k = 0; k < 4; k++) {
      float4 cv = *(const float4*)&sms[D_CS + (w * 4 + k) * 132 + n4 * 4];
      a0[k] = fmaf(cv.x, ha.x, fmaf(cv.y, ha.y, fmaf(cv.z, ha.z, fmaf(cv.w, ha.w, a0[k]))));
      a1[k] = fmaf(cv.x, hb.x, fmaf(cv.y, hb.y, fmaf(cv.z, hb.z, fmaf(cv.w, hb.w, a1[k]))));
    }
  }
#pragma unroll
  for (int k = 0; k < 4; k++) {
    int t = w * 4 + k;
    float et = sms[D_ET + t];
    int row = rowbase + t;
    int col = hh * HD + lane;
    float x0 = g_xc[dir][row][col];
    float x1 = g_xc[dir][row][col + 32];
    g_y[dir][row][col]      = g_y[dir][row][col]      + et * a0[k] + Dh * x0;
    g_y[dir][row][col + 32] = g_y[dir][row][col + 32] + et * a1[k] + Dh * x1;
  }
}

// ---------------- K5: gating + gated RMSNorm -> fp16, both dirs ----------------
__global__ __launch_bounds__(256) void k_gate(const float* __restrict__ gw0,
                                              const float* __restrict__ gw1)
{
  int dir = blockIdx.x >> 12;
  int row = blockIdx.x & 4095;
  int tid = threadIdx.x;
  const float* gnorm_w = dir ? gw1 : gw0;
  float vals[4]; float ss = 0.f;
#pragma unroll
  for (int i = 0; i < 4; i++) {
    int c = tid + i * 256;
    float yv = g_y[dir][row][c];
    float z = __half2float(g_zxh[dir][row][c]);
    float gv = yv * (z / (1.f + expf(-z)));
    vals[i] = gv; ss += gv * gv;
  }
  __shared__ float red[256];
  red[tid] = ss; __syncthreads();
  for (int s = 128; s > 0; s >>= 1) { if (tid < s) red[tid] += red[tid + s]; __syncthreads(); }
  float sc = rsqrtf(red[0] * (1.f / DINNER) + 1e-5f);
#pragma unroll
  for (int i = 0; i < 4; i++) {
    int c = tid + i * 256;
    g_yh[dir][row][c] = __float2half(vals[i] * sc * gnorm_w[c]);
  }
}

// ---------------- launch ----------------
extern "C" void kernel_launch(void* const* d_in, const int* in_sizes, int n_in,
                              void* d_out, int out_size)
{
  (void)in_sizes; (void)n_in; (void)out_size;
  const float* x      = (const float*)d_in[0];
  const float* norm_w = (const float*)d_in[1];
  const float* op_w   = (const float*)d_in[2];
  const float* op_b   = (const float*)d_in[3];
  const float* in_w[2]    = {(const float*)d_in[4],  (const float*)d_in[12]};
  const float* conv_w[2]  = {(const float*)d_in[5],  (const float*)d_in[13]};
  const float* conv_b[2]  = {(const float*)d_in[6],  (const float*)d_in[14]};
  const float* dt_bias[2] = {(const float*)d_in[7],  (const float*)d_in[15]};
  const float* A_log[2]   = {(const float*)d_in[8],  (const float*)d_in[16]};
  const float* Dvec[2]    = {(const float*)d_in[9],  (const float*)d_in[17]};
  const float* gnorm[2]   = {(const float*)d_in[10], (const float*)d_in[18]};
  const float* outp_w[2]  = {(const float*)d_in[11], (const float*)d_in[19]};
  float* out = (float*)d_out;

  __half *pwi, *pwo, *pwp, *puh, *pyh, *podh, *pzxh;
  cudaGetSymbolAddress((void**)&pwi, wh_in);
  cudaGetSymbolAddress((void**)&pwo, wh_out);
  cudaGetSymbolAddress((void**)&pwp, wh_op);
  cudaGetSymbolAddress((void**)&puh, g_uh);
  cudaGetSymbolAddress((void**)&pyh, g_yh);
  cudaGetSymbolAddress((void**)&podh, g_odh);
  cudaGetSymbolAddress((void**)&pzxh, g_zxh);

  static int attr_set = 0;
  if (!attr_set) {
    cudaFuncSetAttribute(k_gemm_h, cudaFuncAttributeMaxDynamicSharedMemorySize, GSMEM);
    cudaFuncSetAttribute(k_ssd_a,  cudaFuncAttributeMaxDynamicSharedMemorySize, A_SMEM);
    cudaFuncSetAttribute(k_ssd_d,  cudaFuncAttributeMaxDynamicSharedMemorySize, D_SMEM);
    attr_set = 1;
  }

  // 1: weight convert + rmsnorm (fused)
  k_pre<<<dim3(BL, 6), 256>>>(
      x, norm_w,
      in_w[0],   pwi,                  DPROJ * DHALF,
      in_w[1],   pwi + DPROJ * DHALF,  DPROJ * DHALF,
      outp_w[0], pwo,                  DHALF * DINNER,
      outp_w[1], pwo + DHALF * DINNER, DHALF * DINNER,
      op_w,      pwp,                  DMODEL * DMODEL);

  // 2: in-proj, both dirs, fp16 output
  k_gemm_h<<<dim3((DPROJ + 127) / 128, BL / 128, 2), 128, GSMEM>>>(
      puh, pwi, nullptr, nullptr, nullptr, pzxh,
      DPROJ, DHALF, DPROJ, 0, 0, 0,
      (size_t)BL * DHALF, (size_t)DPROJ * DHALF, (size_t)BL * DPROJ);

  // 3: conv
  k_conv<<<2 * BL, 256>>>(conv_w[0], conv_b[0], dt_bias[0], A_log[0],
                          conv_w[1], conv_b[1], dt_bias[1], A_log[1]);

  // 4-6: chunked-SSD scan
  k_ssd_a<<<dim3(NCH, DBH), 256, A_SMEM>>>();
  k_ssd_rec<<<DBH * 32, 256>>>();
  k_ssd_d<<<dim3(NCH, DBH), 256, D_SMEM>>>(Dvec[0], Dvec[1]);

  // 7: gate
  k_gate<<<2 * BL, 256>>>(gnorm[0], gnorm[1]);

  // 8: out-proj, both dirs
  k_gemm_h<<<dim3(DHALF / 128, BL / 128, 2), 128, GSMEM>>>(
      pyh, pwo, nullptr, nullptr, nullptr, podh,
      DHALF, DINNER, DMODEL, 0, DHALF, 1,
      (size_t)BL * DINNER, (size_t)DHALF * DINNER, 0);

  // 9: final projection (+bias, +residual x)
  k_gemm_h<<<dim3(DMODEL / 128, BL / 128, 1), 128, GSMEM>>>(
      podh, pwp, op_b, x, out, nullptr,
      DMODEL, DMODEL, DMODEL, 0, 0, 0, 0, 0, 0);
}